// round 1
// baseline (speedup 1.0000x reference)
#include <cuda_runtime.h>

// Multi-scale 3D LNCC (MermaidNet similarity), separable box-sum formulation.
// Scales: (k=12,s=3,OD=57), (k=24,s=6,OD=25), (k=48,s=12,OD=9); dilation=2 all axes.
// sim = sum_scales w * (1 - mean(lncc))

#define IMG 192
#define IMG2 (IMG * IMG)

// Scratch (static device globals; no allocation at runtime).
// Max sizes are for scale 0 (OD=57).
__device__ float  g_T1[5 * 57 * IMG * IMG];   // [c][od][h][w]  (sum over D)   ~42 MB
__device__ float  g_T2[5 * 57 * 57 * IMG];    // [c][od][oh][w] (sum over D,H) ~12.5 MB
__device__ double g_acc;

__global__ void init_kernel() {
    // sim = (sum of weights) - sum_s (w_s/count_s) * sum(lncc_s)
    g_acc = 1.0;  // 0.1 + 0.3 + 0.6
}

// Pass 1: for each (od, h, w): sum over i of f(od*s + 2i, h, w), 5 channels fused.
template <int K, int S, int OD>
__global__ void pass1_kernel(const float* __restrict__ I, const float* __restrict__ T) {
    const int od = blockIdx.x;
    const int h  = blockIdx.y;
    const int w  = threadIdx.x;

    float si = 0.f, st = 0.f, si2 = 0.f, st2 = 0.f, sit = 0.f;
    const int dbase = od * S;
#pragma unroll
    for (int i = 0; i < K; ++i) {
        const int idx = (dbase + 2 * i) * IMG2 + h * IMG + w;
        const float vi = I[idx];
        const float vt = T[idx];
        si  += vi;
        st  += vt;
        si2 += vi * vi;
        st2 += vt * vt;
        sit += vi * vt;
    }
    const int chs = OD * IMG2;
    const int o   = (od * IMG + h) * IMG + w;
    g_T1[o          ] = si;
    g_T1[o +     chs] = st;
    g_T1[o + 2 * chs] = si2;
    g_T1[o + 3 * chs] = st2;
    g_T1[o + 4 * chs] = sit;
}

// Pass 2: for each (od, oh, w): sum over j of T1[c][od][oh*s + 2j][w].
template <int K, int S, int OD>
__global__ void pass2_kernel() {
    const int od = blockIdx.x;
    const int oh = blockIdx.y;
    const int w  = threadIdx.x;

    const int chs1 = OD * IMG2;
    const int chs2 = OD * OD * IMG;
    const int hbase = oh * S;

#pragma unroll
    for (int c = 0; c < 5; ++c) {
        float acc = 0.f;
        const int b = c * chs1 + od * IMG2 + hbase * IMG + w;
#pragma unroll
        for (int j = 0; j < K; ++j) {
            acc += g_T1[b + (2 * j) * IMG];
        }
        g_T2[c * chs2 + (od * OD + oh) * IMG + w] = acc;
    }
}

// Pass 3: for each output voxel, sum over W axis, compute lncc, block-reduce mean.
template <int K, int S, int OD>
__global__ void pass3_kernel(double neg_w_over_count) {
    const int tid   = blockIdx.x * blockDim.x + threadIdx.x;
    const int total = OD * OD * OD;

    float lncc = 0.f;
    if (tid < total) {
        const int od  = tid / (OD * OD);
        const int rem = tid - od * OD * OD;
        const int oh  = rem / OD;
        const int ow  = rem - oh * OD;

        const int chs2    = OD * OD * IMG;
        const int rowbase = (od * OD + oh) * IMG + ow * S;

        float s[5];
#pragma unroll
        for (int c = 0; c < 5; ++c) {
            float acc = 0.f;
            const int b = c * chs2 + rowbase;
#pragma unroll
            for (int l = 0; l < K; ++l) {
                acc += g_T2[b + 2 * l];
            }
            s[c] = acc;
        }
        const float numel = (float)K * (float)K * (float)K;
        const float cross = s[4] - s[0] * s[1] / numel;
        const float ivar  = s[2] - s[0] * s[0] / numel;
        const float tvar  = s[3] - s[1] * s[1] / numel;
        lncc = cross * cross / (ivar * tvar + 1e-5f);
    }

    __shared__ float sh[256];
    sh[threadIdx.x] = lncc;
    __syncthreads();
#pragma unroll
    for (int off = 128; off > 0; off >>= 1) {
        if (threadIdx.x < off) sh[threadIdx.x] += sh[threadIdx.x + off];
        __syncthreads();
    }
    if (threadIdx.x == 0) {
        atomicAdd(&g_acc, neg_w_over_count * (double)sh[0]);
    }
}

__global__ void final_kernel(float* __restrict__ out) {
    out[0] = (float)g_acc;
}

template <int K, int S, int OD>
static void run_scale(const float* I0, const float* I1, double weight) {
    pass1_kernel<K, S, OD><<<dim3(OD, IMG), IMG>>>(I0, I1);
    pass2_kernel<K, S, OD><<<dim3(OD, OD), IMG>>>();
    const int total = OD * OD * OD;
    pass3_kernel<K, S, OD><<<(total + 255) / 256, 256>>>(-weight / (double)total);
}

extern "C" void kernel_launch(void* const* d_in, const int* in_sizes, int n_in,
                              void* d_out, int out_size) {
    const float* I0 = (const float*)d_in[0];
    const float* I1 = (const float*)d_in[1];
    float* out = (float*)d_out;

    init_kernel<<<1, 1>>>();
    run_scale<12, 3, 57>(I0, I1, 0.1);
    run_scale<24, 6, 25>(I0, I1, 0.3);
    run_scale<48, 12, 9>(I0, I1, 0.6);
    final_kernel<<<1, 1>>>(out);
}

// round 5
// speedup vs baseline: 1.1439x; 1.1439x over previous
#include <cuda_runtime.h>

// Multi-scale 3D LNCC (MermaidNet similarity).
// Scales: (k=12,s=3,OD=57), (k=24,s=6,OD=25), (k=48,s=12,OD=9); dilation=2.
// sim = sum_s w_s * (1 - mean(lncc_s))
//
// Sliding-window D-pass (each input element read <=2x instead of Kx),
// fused H-pass + W-pass + LNCC + reduction (intermediate T2 eliminated).

#define IMG 192
#define IMG2 (IMG * IMG)

// Scratch: D-summed tensor for the current scale, [c][od][h][w]. Max: OD=57.
__device__ float  g_T1[5 * 57 * IMG * IMG];   // ~42 MB
__device__ double g_acc;

__global__ void init_kernel() {
    // sim = (sum of weights) - sum_s (w_s/count_s) * sum(lncc_s)
    g_acc = 1.0;  // 0.1 + 0.3 + 0.6
}

// ---------------------------------------------------------------------------
// Pass 1 (sum over D), sliding window along same-parity od chains.
// Window for output od: positions d = od*S + 2*i, i in [0, K).
// Chain period P = (S odd ? 2 : 1); per slide, SH = P*S/2 elements leave and
// SH elements enter. Thread = (h, w) column for one parity chain.
// ---------------------------------------------------------------------------
template <int K, int S, int OD>
__global__ void pass1_kernel(const float* __restrict__ I, const float* __restrict__ T) {
    constexpr int P  = (S % 2 == 0) ? 1 : 2;
    constexpr int SH = P * S / 2;

    const int h = blockIdx.x;
    const int p = blockIdx.y;           // parity (0 for even S)
    const int w = threadIdx.x;
    const int col = h * IMG + w;

    constexpr int chs = OD * IMG2;

    float si = 0.f, st = 0.f, si2 = 0.f, st2 = 0.f, sit = 0.f;

    // Build initial window at od = p.
    {
        const int d0 = p * S;
#pragma unroll
        for (int i = 0; i < K; ++i) {
            const int idx = (d0 + 2 * i) * IMG2 + col;
            const float vi = I[idx];
            const float vt = T[idx];
            si += vi; st += vt; si2 += vi * vi; st2 += vt * vt; sit += vi * vt;
        }
    }

    for (int od = p; ; od += P) {
        const int o = od * IMG2 + col;
        g_T1[o          ] = si;
        g_T1[o +     chs] = st;
        g_T1[o + 2 * chs] = si2;
        g_T1[o + 3 * chs] = st2;
        g_T1[o + 4 * chs] = sit;

        if (od + P >= OD) break;

        const int base_old = od * S;   // window start we are leaving
#pragma unroll
        for (int t = 0; t < SH; ++t) {
            {   // subtract outgoing element i = t
                const int idx = (base_old + 2 * t) * IMG2 + col;
                const float vi = I[idx];
                const float vt = T[idx];
                si -= vi; st -= vt; si2 -= vi * vi; st2 -= vt * vt; sit -= vi * vt;
            }
            {   // add incoming element i = K + t
                const int idx = (base_old + 2 * (K + t)) * IMG2 + col;
                const float vi = I[idx];
                const float vt = T[idx];
                si += vi; st += vt; si2 += vi * vi; st2 += vt * vt; sit += vi * vt;
            }
        }
    }
}

// ---------------------------------------------------------------------------
// Fused pass 2+3: block per (od, oh). Phase 1: coalesced H-window sums of T1
// into smem row. Phase 2: W-window + LNCC from smem, warp reduce, one atomic.
// ---------------------------------------------------------------------------
template <int K, int S, int OD>
__global__ void pass23_kernel(double neg_w_over_count) {
    const int od = blockIdx.x;
    const int oh = blockIdx.y;
    const int w  = threadIdx.x;           // 192 threads

    constexpr int chs = OD * IMG2;
    __shared__ float sh[5][IMG];

    // Phase 1: H-window sums, coalesced over w.
    const int hbase = oh * S;
    const float* __restrict__ base0 = &g_T1[od * IMG2 + hbase * IMG + w];
#pragma unroll
    for (int c = 0; c < 5; ++c) {
        const float* __restrict__ bc = base0 + c * chs;
        float acc = 0.f;
#pragma unroll
        for (int j = 0; j < K; ++j) {
            acc += bc[2 * j * IMG];
        }
        sh[c][w] = acc;
    }
    __syncthreads();

    // Phase 2: W-window + LNCC (only first OD threads produce values).
    float lncc = 0.f;
    if (w < OD) {
        const int wbase = w * S;
        float s[5];
#pragma unroll
        for (int c = 0; c < 5; ++c) {
            float acc = 0.f;
#pragma unroll
            for (int l = 0; l < K; ++l) {
                acc += sh[c][wbase + 2 * l];
            }
            s[c] = acc;
        }
        const float numel = (float)K * (float)K * (float)K;
        const float cross = s[4] - s[0] * s[1] / numel;
        const float ivar  = s[2] - s[0] * s[0] / numel;
        const float tvar  = s[3] - s[1] * s[1] / numel;
        lncc = cross * cross / (ivar * tvar + 1e-5f);
    }

    // Reduce: OD <= 57, so only warps 0 and 1 carry nonzero values.
#pragma unroll
    for (int o = 16; o > 0; o >>= 1)
        lncc += __shfl_down_sync(0xffffffffu, lncc, o);

    __shared__ float wsum[2];
    if (w == 0)  wsum[0] = lncc;
    if (w == 32) wsum[1] = lncc;
    __syncthreads();
    if (w == 0) {
        atomicAdd(&g_acc, neg_w_over_count * (double)(wsum[0] + wsum[1]));
    }
}

__global__ void final_kernel(float* __restrict__ out) {
    out[0] = (float)g_acc;
}

template <int K, int S, int OD>
static void run_scale(const float* I0, const float* I1, double weight) {
    constexpr int P = (S % 2 == 0) ? 1 : 2;
    pass1_kernel<K, S, OD><<<dim3(IMG, P), IMG>>>(I0, I1);
    const int total = OD * OD * OD;
    pass23_kernel<K, S, OD><<<dim3(OD, OD), IMG>>>(-weight / (double)total);
}

extern "C" void kernel_launch(void* const* d_in, const int* in_sizes, int n_in,
                              void* d_out, int out_size) {
    const float* I0 = (const float*)d_in[0];
    const float* I1 = (const float*)d_in[1];
    float* out = (float*)d_out;

    init_kernel<<<1, 1>>>();
    run_scale<12, 3, 57>(I0, I1, 0.1);
    run_scale<24, 6, 25>(I0, I1, 0.3);
    run_scale<48, 12, 9>(I0, I1, 0.6);
    final_kernel<<<1, 1>>>(out);
}

// round 10
// speedup vs baseline: 1.3771x; 1.2038x over previous
#include <cuda_runtime.h>

// Multi-scale 3D LNCC (MermaidNet similarity).
// Scales: (k=12,s=3,OD=57), (k=24,s=6,OD=25), (k=48,s=12,OD=9); dilation=2.
// sim = sum_s w_s * (1 - mean(lncc_s))
//
// Segmented sliding-window D-pass + ALL scales fused into single
// pass1 / pass23 launches (separate scratch per scale) to fix the 11%
// occupancy / serialization bottleneck seen in ncu round 5.

#define IMG 192
#define IMG2 (IMG * IMG)

// Per-scale scratch: D-summed tensors [c][od][h][w].
__device__ float  g_T1a[5 * 57 * IMG2];   // ~42 MB  (k=12)
__device__ float  g_T1b[5 * 25 * IMG2];   // ~18 MB  (k=24)
__device__ float  g_T1c[5 *  9 * IMG2];   // ~6.6 MB (k=48)
__device__ double g_acc;

__global__ void init_kernel() {
    g_acc = 1.0;   // sum of weights; lncc means are subtracted
}

// ---------------------------------------------------------------------------
// Pass 1 segment: sliding-window sum over D for a slice of the od-chain.
// Chain: od = p + P*i. Window for od: d = od*S + 2*k, k in [0,K).
// Slide od -> od+P removes SH = P*S/2 dilated elements, adds SH.
// ---------------------------------------------------------------------------
template <int K, int S, int OD, int P, int SEGLEN>
__device__ __forceinline__ void pass1_seg(
    const float* __restrict__ I, const float* __restrict__ T,
    float* __restrict__ T1, int h, int p, int seg)
{
    constexpr int SH  = P * S / 2;
    constexpr int chs = OD * IMG2;

    const int w   = threadIdx.x;
    const int col = h * IMG + w;

    const int L  = (OD - p + P - 1) / P;        // chain length for this parity
    const int i0 = seg * SEGLEN;
    if (i0 >= L) return;
    const int iend = (i0 + SEGLEN < L) ? (i0 + SEGLEN) : L;

    int od = p + P * i0;

    float si = 0.f, st = 0.f, si2 = 0.f, st2 = 0.f, sit = 0.f;
    {
        const int d0 = od * S;
#pragma unroll
        for (int i = 0; i < K; ++i) {
            const int idx = (d0 + 2 * i) * IMG2 + col;
            const float vi = I[idx];
            const float vt = T[idx];
            si += vi; st += vt; si2 += vi * vi; st2 += vt * vt; sit += vi * vt;
        }
    }

    for (int i = i0; ; ) {
        const int o = od * IMG2 + col;
        T1[o          ] = si;
        T1[o +     chs] = st;
        T1[o + 2 * chs] = si2;
        T1[o + 3 * chs] = st2;
        T1[o + 4 * chs] = sit;

        if (++i >= iend) break;

        const int base_old = od * S;
#pragma unroll
        for (int t = 0; t < SH; ++t) {
            {
                const int idx = (base_old + 2 * t) * IMG2 + col;
                const float vi = I[idx];
                const float vt = T[idx];
                si -= vi; st -= vt; si2 -= vi * vi; st2 -= vt * vt; sit -= vi * vt;
            }
            {
                const int idx = (base_old + 2 * (K + t)) * IMG2 + col;
                const float vi = I[idx];
                const float vt = T[idx];
                si += vi; st += vt; si2 += vi * vi; st2 += vt * vt; sit += vi * vt;
            }
        }
        od += P;
    }
}

// Block layout: scale0: 192h * 2p * 4seg = 1536; scale1: 192h * 5seg = 960;
// scale2: 192h * 3seg = 576. Total 3072 blocks, 192 threads each.
__global__ void pass1_all(const float* __restrict__ I, const float* __restrict__ T) {
    int b = blockIdx.x;
    if (b < 1536) {
        const int h = b % IMG;
        const int r = b / IMG;          // 0..7
        pass1_seg<12, 3, 57, 2, 8>(I, T, g_T1a, h, r & 1, r >> 1);
    } else if (b < 1536 + 960) {
        b -= 1536;
        pass1_seg<24, 6, 25, 1, 5>(I, T, g_T1b, b % IMG, 0, b / IMG);
    } else {
        b -= 1536 + 960;
        pass1_seg<48, 12, 9, 1, 3>(I, T, g_T1c, b % IMG, 0, b / IMG);
    }
}

// ---------------------------------------------------------------------------
// Fused pass 2+3 for one (od, oh): coalesced H-window sums into smem,
// W-window + LNCC, warp reduce, one double atomic.
// ---------------------------------------------------------------------------
template <int K, int S, int OD>
__device__ __forceinline__ void pass23_scale(
    const float* __restrict__ T1, int od, int oh, double neg_w_over_count)
{
    constexpr int chs = OD * IMG2;
    const int w = threadIdx.x;            // 192 threads

    __shared__ float sh[5][IMG];

    const int hbase = oh * S;
    const float* __restrict__ base0 = &T1[od * IMG2 + hbase * IMG + w];
#pragma unroll
    for (int c = 0; c < 5; ++c) {
        const float* __restrict__ bc = base0 + c * chs;
        float acc = 0.f;
#pragma unroll
        for (int j = 0; j < K; ++j) {
            acc += bc[2 * j * IMG];
        }
        sh[c][w] = acc;
    }
    __syncthreads();

    float lncc = 0.f;
    if (w < OD) {
        const int wbase = w * S;
        float s[5];
#pragma unroll
        for (int c = 0; c < 5; ++c) {
            float acc = 0.f;
#pragma unroll
            for (int l = 0; l < K; ++l) {
                acc += sh[c][wbase + 2 * l];
            }
            s[c] = acc;
        }
        const float numel = (float)K * (float)K * (float)K;
        const float cross = s[4] - s[0] * s[1] / numel;
        const float ivar  = s[2] - s[0] * s[0] / numel;
        const float tvar  = s[3] - s[1] * s[1] / numel;
        lncc = cross * cross / (ivar * tvar + 1e-5f);
    }

#pragma unroll
    for (int o = 16; o > 0; o >>= 1)
        lncc += __shfl_down_sync(0xffffffffu, lncc, o);

    __shared__ float wsum[2];
    if (w == 0)  wsum[0] = lncc;
    if (w == 32) wsum[1] = lncc;
    __syncthreads();
    if (w == 0) {
        atomicAdd(&g_acc, neg_w_over_count * (double)(wsum[0] + wsum[1]));
    }
}

// Block layout: scale0: 57*57=3249; scale1: 625; scale2: 81. Total 3955.
__global__ void pass23_all() {
    int b = blockIdx.x;
    if (b < 3249) {
        pass23_scale<12, 3, 57>(g_T1a, b / 57, b % 57, -0.1 / 185193.0);
    } else if (b < 3249 + 625) {
        b -= 3249;
        pass23_scale<24, 6, 25>(g_T1b, b / 25, b % 25, -0.3 / 15625.0);
    } else {
        b -= 3249 + 625;
        pass23_scale<48, 12, 9>(g_T1c, b / 9, b % 9, -0.6 / 729.0);
    }
}

__global__ void final_kernel(float* __restrict__ out) {
    out[0] = (float)g_acc;
}

extern "C" void kernel_launch(void* const* d_in, const int* in_sizes, int n_in,
                              void* d_out, int out_size) {
    const float* I0 = (const float*)d_in[0];
    const float* I1 = (const float*)d_in[1];
    float* out = (float*)d_out;

    init_kernel<<<1, 1>>>();
    pass1_all<<<3072, IMG>>>(I0, I1);
    pass23_all<<<3955, IMG>>>();
    final_kernel<<<1, 1>>>(out);
}